// round 6
// baseline (speedup 1.0000x reference)
#include <cuda_runtime.h>
#include <cuda_bf16.h>
#include <cstdint>

// ---------------- problem constants ----------------
#define BROWS   65536
#define DDIM    1024
#define NCOLS   128        // 120 real columns padded to 128
#define KC      32         // K elems per chunk
#define NCHUNK  (DDIM / KC)    // 32
#define TILE_M  128
#define STAGES  3
#define PITCHA  40         // A stage pitch in floats (160B) -> conflict-free LDS.64
#define PITCHB  40         // B stage pitch in bf16 (80B)    -> conflict-free LDS.32
#define OPAD    130        // out-tile row pitch (floats)

#define ASTG    (TILE_M * PITCHA * 4)   // 20480 B per A stage buffer (fp32)
#define BSTG    (NCOLS  * PITCHB * 2)   // 10240 B per B stage buffer (bf16)
#define BOFF    (STAGES * ASTG)         // 61440
#define SMEM_BYTES (STAGES * (ASTG + BSTG))  // 92160 (>= out tile 66560)

// packed weights: [NCOLS][DDIM] K-major bf16 (256 KB static device array — no alloc)
__device__ __align__(16) __nv_bfloat16 g_Wpack[NCOLS * DDIM];

__device__ __forceinline__ uint32_t smem_u32(const void* p) {
    uint32_t a;
    asm("{ .reg .u64 t; cvta.to.shared.u64 t, %1; cvt.u32.u64 %0, t; }" : "=r"(a) : "l"(p));
    return a;
}
#define CP_ASYNC16(dst_u32, src_ptr) \
    asm volatile("cp.async.cg.shared.global [%0], [%1], 16;" :: "r"(dst_u32), "l"(src_ptr) : "memory")
#define CP_COMMIT() asm volatile("cp.async.commit_group;" ::: "memory")
#define CP_WAIT1()  asm volatile("cp.async.wait_group 1;" ::: "memory")
#define CP_WAIT0()  asm volatile("cp.async.wait_group 0;" ::: "memory")

// ---------------- weight pack kernel ----------------
__global__ void pack_weights_kernel(const float* __restrict__ expert_w,
                                    const float* __restrict__ gate_w) {
    int j = blockIdx.x;                       // 0..127
    for (int d = threadIdx.x; d < DDIM; d += blockDim.x) {
        float v = 0.0f;
        if (j < 100) {
            int e = j / 10, u = j % 10;
            v = expert_w[((size_t)e * DDIM + d) * 10 + u];
        } else if (j < 120) {
            int idx = j - 100;
            int t = idx / 10, e = idx % 10;
            v = gate_w[((size_t)t * DDIM + d) * 10 + e];
        }
        g_Wpack[(size_t)j * DDIM + d] = __float2bfloat16(v);
    }
}

// ---------------- fused MMoE main kernel ----------------
extern "C" __global__ void __launch_bounds__(256, 2)
mmoe_main_kernel(const float* __restrict__ x,
                 const float* __restrict__ expert_b,   // [10,10]
                 const float* __restrict__ gate_b,     // [2,10]
                 const float* __restrict__ ctr_w,      // [10]
                 const float* __restrict__ ctr_b,      // [1]
                 const float* __restrict__ cvr_w,      // [10]
                 const float* __restrict__ cvr_b,      // [1]
                 float* __restrict__ out) {            // [2*B] = [ctr | cvr]
    extern __shared__ char smem[];
    const uint32_t smem_base = smem_u32(smem);
    float* outS = reinterpret_cast<float*>(smem);

    const int tid  = threadIdx.x;
    const int wid  = tid >> 5;
    const int lane = tid & 31;
    const int gid  = lane >> 2;   // 0..7
    const int tig  = lane & 3;    // 0..3
    const int warp_m = (wid & 3) * 32;   // 4 warps along M
    const int warp_n = (wid >> 2) * 64;  // 2 warps along N
    const int row0 = blockIdx.x * TILE_M;

    // cp.async mapping:  A: 4 ops/thread (128 rows x 8 x16B), B: 2 ops/thread (128 x 4 x16B)
    const int arow = tid >> 3;          // with +32*it: rows 0..127 over 4 its? (see loop)
    const int ac16 = tid & 7;
    const int brow = tid >> 2;          // with +64*it
    const int bc16 = tid & 3;

    float acc[2][8][4];
    #pragma unroll
    for (int mt = 0; mt < 2; ++mt)
        #pragma unroll
        for (int nt = 0; nt < 8; ++nt)
            #pragma unroll
            for (int i = 0; i < 4; ++i) acc[mt][nt][i] = 0.0f;

    // ---- issue one chunk's loads into stage buffer s ----
    auto issue_chunk = [&](int c, int s) {
        const int k0 = c * KC;
        const uint32_t ab = smem_base + s * ASTG;
        #pragma unroll
        for (int it = 0; it < 4; ++it) {
            const int r = arow + it * 32;
            CP_ASYNC16(ab + (uint32_t)(r * PITCHA + ac16 * 4) * 4,
                       x + (size_t)(row0 + r) * DDIM + k0 + ac16 * 4);
        }
        const uint32_t bb = smem_base + BOFF + s * BSTG;
        #pragma unroll
        for (int it = 0; it < 2; ++it) {
            const int r = brow + it * 64;
            CP_ASYNC16(bb + (uint32_t)(r * PITCHB + bc16 * 8) * 2,
                       g_Wpack + (size_t)r * DDIM + k0 + bc16 * 8);
        }
        CP_COMMIT();
    };

    // ---- prologue: stages 0,1 in flight ----
    issue_chunk(0, 0);
    issue_chunk(1, 1);

    int sc = 0;                       // stage index of chunk c (c % STAGES)
    for (int c = 0; c < NCHUNK; ++c) {
        if (c == NCHUNK - 1) { CP_WAIT0(); } else { CP_WAIT1(); }   // chunk c landed
        __syncthreads();              // all warps done with buffer being refilled next

        if (c + STAGES - 1 < NCHUNK) {
            int sn = sc + STAGES - 1; if (sn >= STAGES) sn -= STAGES;
            issue_chunk(c + STAGES - 1, sn);
        }

        const float*         Af = reinterpret_cast<const float*>(smem + sc * ASTG);
        const __nv_bfloat16* Bb = reinterpret_cast<const __nv_bfloat16*>(smem + BOFF + sc * BSTG);

        // ---- compute: 2 k-tiles of 16 ----
        #pragma unroll
        for (int kt = 0; kt < 2; ++kt) {
            const int colk = kt * 16 + tig * 2;
            uint32_t afrag[2][4];
            #pragma unroll
            for (int mt = 0; mt < 2; ++mt) {
                const int mb = warp_m + mt * 16;
                float2 v0 = *reinterpret_cast<const float2*>(Af + (mb + gid)     * PITCHA + colk);
                float2 v1 = *reinterpret_cast<const float2*>(Af + (mb + gid + 8) * PITCHA + colk);
                float2 v2 = *reinterpret_cast<const float2*>(Af + (mb + gid)     * PITCHA + colk + 8);
                float2 v3 = *reinterpret_cast<const float2*>(Af + (mb + gid + 8) * PITCHA + colk + 8);
                __nv_bfloat162 h0 = __floats2bfloat162_rn(v0.x, v0.y);
                __nv_bfloat162 h1 = __floats2bfloat162_rn(v1.x, v1.y);
                __nv_bfloat162 h2 = __floats2bfloat162_rn(v2.x, v2.y);
                __nv_bfloat162 h3 = __floats2bfloat162_rn(v3.x, v3.y);
                afrag[mt][0] = *reinterpret_cast<uint32_t*>(&h0);
                afrag[mt][1] = *reinterpret_cast<uint32_t*>(&h1);
                afrag[mt][2] = *reinterpret_cast<uint32_t*>(&h2);
                afrag[mt][3] = *reinterpret_cast<uint32_t*>(&h3);
            }
            #pragma unroll
            for (int nt = 0; nt < 8; ++nt) {
                const int n = warp_n + nt * 8 + gid;
                const uint32_t b0 = *reinterpret_cast<const uint32_t*>(Bb + n * PITCHB + colk);
                const uint32_t b1 = *reinterpret_cast<const uint32_t*>(Bb + n * PITCHB + colk + 8);
                #pragma unroll
                for (int mt = 0; mt < 2; ++mt) {
                    asm volatile(
                        "mma.sync.aligned.m16n8k16.row.col.f32.bf16.bf16.f32 "
                        "{%0,%1,%2,%3}, {%4,%5,%6,%7}, {%8,%9}, {%0,%1,%2,%3};"
                        : "+f"(acc[mt][nt][0]), "+f"(acc[mt][nt][1]),
                          "+f"(acc[mt][nt][2]), "+f"(acc[mt][nt][3])
                        : "r"(afrag[mt][0]), "r"(afrag[mt][1]),
                          "r"(afrag[mt][2]), "r"(afrag[mt][3]),
                          "r"(b0), "r"(b1));
                }
            }
        }
        if (++sc == STAGES) sc = 0;
    }
    __syncthreads();   // MMAs done; stage buffers dead -> reuse smem as outS

    // --- scatter accumulators to fp32 out tile ---
    #pragma unroll
    for (int mt = 0; mt < 2; ++mt) {
        #pragma unroll
        for (int nt = 0; nt < 8; ++nt) {
            const int r = warp_m + mt * 16 + gid;
            const int col = warp_n + nt * 8 + tig * 2;
            *reinterpret_cast<float2*>(outS + r * OPAD + col) =
                make_float2(acc[mt][nt][0], acc[mt][nt][1]);
            *reinterpret_cast<float2*>(outS + (r + 8) * OPAD + col) =
                make_float2(acc[mt][nt][2], acc[mt][nt][3]);
        }
    }
    __syncthreads();

    // --- per-row epilogue: softmax gates, expert mix, sigmoid heads ---
    if (tid < TILE_M) {
        const float* rowv = outS + tid * OPAD;

        float g[2][10];
        #pragma unroll
        for (int t = 0; t < 2; ++t) {
            float s = 0.0f;
            #pragma unroll
            for (int e = 0; e < 10; ++e) {
                float l = rowv[100 + t * 10 + e] + gate_b[t * 10 + e];
                float ex = expf(l);
                g[t][e] = ex; s += ex;
            }
            float inv = 1.0f / s;
            #pragma unroll
            for (int e = 0; e < 10; ++e) g[t][e] *= inv;
        }

        float ti0[10], ti1[10];
        #pragma unroll
        for (int u = 0; u < 10; ++u) { ti0[u] = 0.0f; ti1[u] = 0.0f; }
        #pragma unroll
        for (int e = 0; e < 10; ++e) {
            const float g0 = g[0][e], g1 = g[1][e];
            #pragma unroll
            for (int u = 0; u < 10; ++u) {
                const int j = e * 10 + u;
                float v = fmaxf(rowv[j] + expert_b[j], 0.0f);
                ti0[u] += v * g0;
                ti1[u] += v * g1;
            }
        }

        float zc = ctr_b[0], zv = cvr_b[0];
        #pragma unroll
        for (int u = 0; u < 10; ++u) {
            zc += ti0[u] * ctr_w[u];
            zv += ti1[u] * cvr_w[u];
        }
        const int gr = row0 + tid;
        out[gr]         = 1.0f / (1.0f + expf(-zc));
        out[BROWS + gr] = 1.0f / (1.0f + expf(-zv));
    }
}

// ---------------- launch ----------------
extern "C" void kernel_launch(void* const* d_in, const int* in_sizes, int n_in,
                              void* d_out, int out_size) {
    const float* x        = (const float*)d_in[0];
    const float* expert_w = (const float*)d_in[3];
    const float* expert_b = (const float*)d_in[4];
    const float* gate_w   = (const float*)d_in[5];
    const float* gate_b   = (const float*)d_in[6];
    const float* ctr_w    = (const float*)d_in[7];
    const float* ctr_b    = (const float*)d_in[8];
    const float* cvr_w    = (const float*)d_in[9];
    const float* cvr_b    = (const float*)d_in[10];
    float* out = (float*)d_out;

    cudaFuncSetAttribute(mmoe_main_kernel,
                         cudaFuncAttributeMaxDynamicSharedMemorySize, SMEM_BYTES);

    pack_weights_kernel<<<NCOLS, 256>>>(expert_w, gate_w);
    mmoe_main_kernel<<<BROWS / TILE_M, 256, SMEM_BYTES>>>(
        x, expert_b, gate_b, ctr_w, ctr_b, cvr_w, cvr_b, out);
}

// round 7
// speedup vs baseline: 1.0878x; 1.0878x over previous
#include <cuda_runtime.h>
#include <cuda_bf16.h>
#include <cstdint>

// ---------------- problem constants ----------------
#define BROWS   65536
#define DDIM    1024
#define NCOLS   128      // 120 real columns padded to 128
#define KC      64       // K elems staged per chunk
#define NCHUNK  (DDIM / KC)   // 16
#define TILE_M  64
#define APAD    72       // smem row pitch (bf16 elems): conflict-free frag LDS
#define OPAD    130      // out-tile row pitch (floats)

#define ABYTES  (TILE_M * APAD * 2)     // 9216 per A buffer
#define BOFF    (2 * ABYTES)            // 18432
#define BBYTES  (NCOLS * APAD * 2)      // 18432 per B buffer
#define SMEM_BYTES (BOFF + 2 * BBYTES)  // 55296 (>= out tile 64*130*4=33280)

// packed weights: [NCOLS][DDIM] K-major bf16 (256 KB static device array — no alloc)
__device__ __align__(16) __nv_bfloat16 g_Wpack[NCOLS * DDIM];

__device__ __forceinline__ uint32_t smem_u32(const void* p) {
    uint32_t a;
    asm("{ .reg .u64 t; cvta.to.shared.u64 t, %1; cvt.u32.u64 %0, t; }" : "=r"(a) : "l"(p));
    return a;
}
#define CP_ASYNC16(dst_u32, src_ptr) \
    asm volatile("cp.async.cg.shared.global [%0], [%1], 16;" :: "r"(dst_u32), "l"(src_ptr) : "memory")
#define CP_COMMIT() asm volatile("cp.async.commit_group;" ::: "memory")
#define CP_WAIT0()  asm volatile("cp.async.wait_group 0;" ::: "memory")

// ---------------- weight pack kernel (grid 128 x 8, 128 thr) ----------------
__global__ void pack_weights_kernel(const float* __restrict__ expert_w,
                                    const float* __restrict__ gate_w) {
    const int j = blockIdx.x;                          // 0..127 (output col)
    const int d = blockIdx.y * 128 + threadIdx.x;      // 0..1023
    float v = 0.0f;
    if (j < 100) {
        int e = j / 10, u = j % 10;
        v = expert_w[((size_t)e * DDIM + d) * 10 + u];
    } else if (j < 120) {
        int idx = j - 100;
        int t = idx / 10, e = idx % 10;
        v = gate_w[((size_t)t * DDIM + d) * 10 + e];
    }
    g_Wpack[(size_t)j * DDIM + d] = __float2bfloat16(v);
}

// ---------------- fused MMoE main kernel (64x128 tile, 3 CTAs/SM) ----------------
extern "C" __global__ void __launch_bounds__(256, 3)
mmoe_main_kernel(const float* __restrict__ x,
                 const float* __restrict__ expert_b,   // [10,10]
                 const float* __restrict__ gate_b,     // [2,10]
                 const float* __restrict__ ctr_w,      // [10]
                 const float* __restrict__ ctr_b,      // [1]
                 const float* __restrict__ cvr_w,      // [10]
                 const float* __restrict__ cvr_b,      // [1]
                 float* __restrict__ out) {            // [2*B] = [ctr | cvr]
    extern __shared__ char smem[];
    const uint32_t smem_base = smem_u32(smem);
    float* outS = reinterpret_cast<float*>(smem);

    const int tid  = threadIdx.x;
    const int wid  = tid >> 5;
    const int lane = tid & 31;
    const int gid  = lane >> 2;   // 0..7
    const int tig  = lane & 3;    // 0..3
    const int warp_m = (wid & 1) * 32;    // 2 warps along M (64 rows)
    const int warp_n = (wid >> 1) * 32;   // 4 warps along N (128 cols)
    const int row0 = blockIdx.x * TILE_M;

    // load-mapping ids
    const int rbase = tid >> 4;          // A: 0..15, rows rbase + it*16 (it<4)
    const int c4    = tid & 15;          // col float4
    const int brb   = tid >> 3;          // B: 0..31, rows brb + it*32 (it<4)
    const int c8    = tid & 7;           // col uint4

    float acc[2][4][4];
    #pragma unroll
    for (int mt = 0; mt < 2; ++mt)
        #pragma unroll
        for (int nt = 0; nt < 4; ++nt)
            #pragma unroll
            for (int i = 0; i < 4; ++i) acc[mt][nt][i] = 0.0f;

    // ---- prologue: prefetch chunk 0 ----
    float4 av[4];
    #pragma unroll
    for (int it = 0; it < 4; ++it)
        av[it] = *reinterpret_cast<const float4*>(
            x + (size_t)(row0 + rbase + it * 16) * DDIM + c4 * 4);
    {
        const uint32_t bb = smem_base + BOFF;         // bbuf[0]
        #pragma unroll
        for (int it = 0; it < 4; ++it)
            CP_ASYNC16(bb + (uint32_t)((brb + it * 32) * APAD + c8 * 8) * 2,
                       g_Wpack + (size_t)(brb + it * 32) * DDIM + c8 * 8);
        CP_COMMIT();
    }

    for (int c = 0; c < NCHUNK; ++c) {
        __nv_bfloat16* Ab = reinterpret_cast<__nv_bfloat16*>(smem + (c & 1) * ABYTES);
        __nv_bfloat16* Bb = reinterpret_cast<__nv_bfloat16*>(smem + BOFF + (c & 1) * BBYTES);

        // ---- STS: convert prefetched A regs -> abuf[c&1] ----
        #pragma unroll
        for (int it = 0; it < 4; ++it) {
            __nv_bfloat162 lo = __floats2bfloat162_rn(av[it].x, av[it].y);
            __nv_bfloat162 hi = __floats2bfloat162_rn(av[it].z, av[it].w);
            uint2 pk;
            pk.x = *reinterpret_cast<uint32_t*>(&lo);
            pk.y = *reinterpret_cast<uint32_t*>(&hi);
            *reinterpret_cast<uint2*>(Ab + (rbase + it * 16) * APAD + c4 * 4) = pk;
        }

        // ---- prefetch A chunk c+1 into regs ----
        if (c + 1 < NCHUNK) {
            const int k0n = (c + 1) * KC;
            #pragma unroll
            for (int it = 0; it < 4; ++it)
                av[it] = *reinterpret_cast<const float4*>(
                    x + (size_t)(row0 + rbase + it * 16) * DDIM + k0n + c4 * 4);
        }

        CP_WAIT0();          // B(c) landed (overlapped MMA(c-1))
        __syncthreads();     // A(c)/B(c) staged; prev MMAs retired

        // ---- issue B chunk c+1 (buffer free: all warps past MMA(c-1)) ----
        if (c + 1 < NCHUNK) {
            const int k0n = (c + 1) * KC;
            const uint32_t bb = smem_base + BOFF + ((c + 1) & 1) * BBYTES;
            #pragma unroll
            for (int it = 0; it < 4; ++it)
                CP_ASYNC16(bb + (uint32_t)((brb + it * 32) * APAD + c8 * 8) * 2,
                           g_Wpack + (size_t)(brb + it * 32) * DDIM + k0n + c8 * 8);
            CP_COMMIT();
        }

        // ---- compute: 4 k-tiles of 16 ----
        #pragma unroll
        for (int kt = 0; kt < 4; ++kt) {
            const int colk = kt * 16 + tig * 2;
            uint32_t afrag[2][4];
            #pragma unroll
            for (int mt = 0; mt < 2; ++mt) {
                const int mb = warp_m + mt * 16;
                afrag[mt][0] = *reinterpret_cast<const uint32_t*>(Ab + (mb + gid)     * APAD + colk);
                afrag[mt][1] = *reinterpret_cast<const uint32_t*>(Ab + (mb + gid + 8) * APAD + colk);
                afrag[mt][2] = *reinterpret_cast<const uint32_t*>(Ab + (mb + gid)     * APAD + colk + 8);
                afrag[mt][3] = *reinterpret_cast<const uint32_t*>(Ab + (mb + gid + 8) * APAD + colk + 8);
            }
            #pragma unroll
            for (int nt = 0; nt < 4; ++nt) {
                const int n = warp_n + nt * 8 + gid;
                const uint32_t b0 = *reinterpret_cast<const uint32_t*>(Bb + n * APAD + colk);
                const uint32_t b1 = *reinterpret_cast<const uint32_t*>(Bb + n * APAD + colk + 8);
                #pragma unroll
                for (int mt = 0; mt < 2; ++mt) {
                    asm volatile(
                        "mma.sync.aligned.m16n8k16.row.col.f32.bf16.bf16.f32 "
                        "{%0,%1,%2,%3}, {%4,%5,%6,%7}, {%8,%9}, {%0,%1,%2,%3};"
                        : "+f"(acc[mt][nt][0]), "+f"(acc[mt][nt][1]),
                          "+f"(acc[mt][nt][2]), "+f"(acc[mt][nt][3])
                        : "r"(afrag[mt][0]), "r"(afrag[mt][1]),
                          "r"(afrag[mt][2]), "r"(afrag[mt][3]),
                          "r"(b0), "r"(b1));
                }
            }
        }
    }
    __syncthreads();   // MMAs done; stage buffers dead -> reuse smem as outS

    // --- scatter accumulators to fp32 out tile ---
    #pragma unroll
    for (int mt = 0; mt < 2; ++mt) {
        #pragma unroll
        for (int nt = 0; nt < 4; ++nt) {
            const int r = warp_m + mt * 16 + gid;
            const int col = warp_n + nt * 8 + tig * 2;
            *reinterpret_cast<float2*>(outS + r * OPAD + col) =
                make_float2(acc[mt][nt][0], acc[mt][nt][1]);
            *reinterpret_cast<float2*>(outS + (r + 8) * OPAD + col) =
                make_float2(acc[mt][nt][2], acc[mt][nt][3]);
        }
    }
    __syncthreads();

    // --- per-row epilogue: softmax gates, expert mix, sigmoid heads ---
    if (tid < TILE_M) {
        const float* rowv = outS + tid * OPAD;

        float g[2][10];
        #pragma unroll
        for (int t = 0; t < 2; ++t) {
            float s = 0.0f;
            #pragma unroll
            for (int e = 0; e < 10; ++e) {
                float l = rowv[100 + t * 10 + e] + gate_b[t * 10 + e];
                float ex = expf(l);
                g[t][e] = ex; s += ex;
            }
            float inv = 1.0f / s;
            #pragma unroll
            for (int e = 0; e < 10; ++e) g[t][e] *= inv;
        }

        float ti0[10], ti1[10];
        #pragma unroll
        for (int u = 0; u < 10; ++u) { ti0[u] = 0.0f; ti1[u] = 0.0f; }
        #pragma unroll
        for (int e = 0; e < 10; ++e) {
            const float g0 = g[0][e], g1 = g[1][e];
            #pragma unroll
            for (int u = 0; u < 10; ++u) {
                const int j = e * 10 + u;
                float v = fmaxf(rowv[j] + expert_b[j], 0.0f);
                ti0[u] += v * g0;
                ti1[u] += v * g1;
            }
        }

        float zc = ctr_b[0], zv = cvr_b[0];
        #pragma unroll
        for (int u = 0; u < 10; ++u) {
            zc += ti0[u] * ctr_w[u];
            zv += ti1[u] * cvr_w[u];
        }
        const int gr = row0 + tid;
        out[gr]         = 1.0f / (1.0f + expf(-zc));
        out[BROWS + gr] = 1.0f / (1.0f + expf(-zv));
    }
}

// ---------------- launch ----------------
extern "C" void kernel_launch(void* const* d_in, const int* in_sizes, int n_in,
                              void* d_out, int out_size) {
    const float* x        = (const float*)d_in[0];
    const float* expert_w = (const float*)d_in[3];
    const float* expert_b = (const float*)d_in[4];
    const float* gate_w   = (const float*)d_in[5];
    const float* gate_b   = (const float*)d_in[6];
    const float* ctr_w    = (const float*)d_in[7];
    const float* ctr_b    = (const float*)d_in[8];
    const float* cvr_w    = (const float*)d_in[9];
    const float* cvr_b    = (const float*)d_in[10];
    float* out = (float*)d_out;

    cudaFuncSetAttribute(mmoe_main_kernel,
                         cudaFuncAttributeMaxDynamicSharedMemorySize, SMEM_BYTES);

    pack_weights_kernel<<<dim3(NCOLS, 8), 128>>>(expert_w, gate_w);
    mmoe_main_kernel<<<BROWS / TILE_M, 256, SMEM_BYTES>>>(
        x, expert_b, gate_b, ctr_w, ctr_b, cvr_w, cvr_b, out);
}

// round 8
// speedup vs baseline: 1.1920x; 1.0958x over previous
#include <cuda_runtime.h>
#include <cuda_bf16.h>
#include <cstdint>

// ---------------- problem constants ----------------
#define BROWS   65536
#define DDIM    1024
#define NCOLS   128      // 120 real columns padded to 128
#define KC      64       // K elems staged per chunk
#define NCHUNK  (DDIM / KC)   // 16
#define TILE_M  64
#define APAD    72       // smem row pitch (bf16): 144B rows -> conflict-free LDSM
#define OPAD    130      // out-tile row pitch (floats)

#define ABYTES  (TILE_M * APAD * 2)     // 9216 per A buffer
#define BOFF    (2 * ABYTES)            // 18432
#define BBYTES  (NCOLS * APAD * 2)      // 18432 per B buffer
#define SMEM_BYTES (BOFF + 2 * BBYTES)  // 55296 (>= out tile 64*130*4)

// packed weights: [NCOLS][DDIM] K-major bf16 (256 KB static device array — no alloc)
__device__ __align__(16) __nv_bfloat16 g_Wpack[NCOLS * DDIM];

__device__ __forceinline__ uint32_t smem_u32(const void* p) {
    uint32_t a;
    asm("{ .reg .u64 t; cvta.to.shared.u64 t, %1; cvt.u32.u64 %0, t; }" : "=r"(a) : "l"(p));
    return a;
}
#define CP_ASYNC16(dst_u32, src_ptr) \
    asm volatile("cp.async.cg.shared.global [%0], [%1], 16;" :: "r"(dst_u32), "l"(src_ptr) : "memory")
#define CP_COMMIT() asm volatile("cp.async.commit_group;" ::: "memory")
#define CP_WAIT0()  asm volatile("cp.async.wait_group 0;" ::: "memory")
#define LDSM_X4(r0, r1, r2, r3, addr) \
    asm volatile("ldmatrix.sync.aligned.m8n8.x4.shared.b16 {%0,%1,%2,%3}, [%4];" \
                 : "=r"(r0), "=r"(r1), "=r"(r2), "=r"(r3) : "r"(addr))

// ---------------- weight pack kernel (grid 128 x 8, 128 thr) ----------------
__global__ void pack_weights_kernel(const float* __restrict__ expert_w,
                                    const float* __restrict__ gate_w) {
    const int j = blockIdx.x;                          // 0..127 (output col)
    const int d = blockIdx.y * 128 + threadIdx.x;      // 0..1023
    float v = 0.0f;
    if (j < 100) {
        int e = j / 10, u = j % 10;
        v = expert_w[((size_t)e * DDIM + d) * 10 + u];
    } else if (j < 120) {
        int idx = j - 100;
        int t = idx / 10, e = idx % 10;
        v = gate_w[((size_t)t * DDIM + d) * 10 + e];
    }
    g_Wpack[(size_t)j * DDIM + d] = __float2bfloat16(v);
}

// ---------------- fused MMoE main kernel (64x128 tile, 3 CTAs/SM) ----------------
extern "C" __global__ void __launch_bounds__(256, 3)
mmoe_main_kernel(const float* __restrict__ x,
                 const float* __restrict__ expert_b,   // [10,10]
                 const float* __restrict__ gate_b,     // [2,10]
                 const float* __restrict__ ctr_w,      // [10]
                 const float* __restrict__ ctr_b,      // [1]
                 const float* __restrict__ cvr_w,      // [10]
                 const float* __restrict__ cvr_b,      // [1]
                 float* __restrict__ out) {            // [2*B] = [ctr | cvr]
    extern __shared__ char smem[];
    const uint32_t smem_base = smem_u32(smem);
    float* outS = reinterpret_cast<float*>(smem);

    const int tid  = threadIdx.x;
    const int wid  = tid >> 5;
    const int lane = tid & 31;
    const int gid  = lane >> 2;   // 0..7
    const int tig  = lane & 3;    // 0..3
    const int warp_m = (wid & 1) * 32;    // 2 warps along M (64 rows)
    const int warp_n = (wid >> 1) * 32;   // 4 warps along N (128 cols)
    const int row0 = blockIdx.x * TILE_M;
    const int wstag = wid & 3;            // per-warp kt phase stagger

    // ldmatrix per-lane base byte offsets (within a stage buffer)
    // A x4: sub bit0 -> +8 rows, bit1 -> +16B col.  subs = {a0,a1,a2,a3}
    const uint32_t aLdsmBase =
        (uint32_t)(warp_m + ((lane >> 3) & 1) * 8 + (lane & 7)) * (APAD * 2)
        + ((lane >> 4) & 1) * 16;
    // B x4: sub bit0 -> +16B col, bit1 -> +8 rows.  subs = {b0(nA),b1(nA),b0(nB),b1(nB)}
    const uint32_t bLdsmBase =
        (uint32_t)(warp_n + ((lane >> 4) & 1) * 8 + (lane & 7)) * (APAD * 2)
        + ((lane >> 3) & 1) * 16;

    // load-mapping ids
    const int rbase = tid >> 4;          // A: 0..15, rows rbase + it*16 (it<4)
    const int c4    = tid & 15;          // col float4
    const int brb   = tid >> 3;          // B: 0..31, rows brb + it*32 (it<4)
    const int c8    = tid & 7;           // col uint4

    float acc[2][4][4];
    #pragma unroll
    for (int mt = 0; mt < 2; ++mt)
        #pragma unroll
        for (int nt = 0; nt < 4; ++nt)
            #pragma unroll
            for (int i = 0; i < 4; ++i) acc[mt][nt][i] = 0.0f;

    // ---- prologue: prefetch chunk 0 ----
    float4 av[4];
    #pragma unroll
    for (int it = 0; it < 4; ++it)
        av[it] = *reinterpret_cast<const float4*>(
            x + (size_t)(row0 + rbase + it * 16) * DDIM + c4 * 4);
    {
        const uint32_t bb = smem_base + BOFF;         // bbuf[0]
        #pragma unroll
        for (int it = 0; it < 4; ++it)
            CP_ASYNC16(bb + (uint32_t)((brb + it * 32) * APAD + c8 * 8) * 2,
                       g_Wpack + (size_t)(brb + it * 32) * DDIM + c8 * 8);
        CP_COMMIT();
    }

    for (int c = 0; c < NCHUNK; ++c) {
        __nv_bfloat16* Ab = reinterpret_cast<__nv_bfloat16*>(smem + (c & 1) * ABYTES);
        const uint32_t aStage = smem_base + (c & 1) * ABYTES;
        const uint32_t bStage = smem_base + BOFF + (c & 1) * BBYTES;

        // ---- STS: convert prefetched A regs -> abuf[c&1] ----
        #pragma unroll
        for (int it = 0; it < 4; ++it) {
            __nv_bfloat162 lo = __floats2bfloat162_rn(av[it].x, av[it].y);
            __nv_bfloat162 hi = __floats2bfloat162_rn(av[it].z, av[it].w);
            uint2 pk;
            pk.x = *reinterpret_cast<uint32_t*>(&lo);
            pk.y = *reinterpret_cast<uint32_t*>(&hi);
            *reinterpret_cast<uint2*>(Ab + (rbase + it * 16) * APAD + c4 * 4) = pk;
        }

        // ---- prefetch A chunk c+1 into regs ----
        if (c + 1 < NCHUNK) {
            const int k0n = (c + 1) * KC;
            #pragma unroll
            for (int it = 0; it < 4; ++it)
                av[it] = *reinterpret_cast<const float4*>(
                    x + (size_t)(row0 + rbase + it * 16) * DDIM + k0n + c4 * 4);
        }

        CP_WAIT0();          // B(c) landed (overlapped MMA(c-1))
        __syncthreads();     // A(c)/B(c) staged; prev MMAs retired

        // ---- issue B chunk c+1 (buffer free: all warps past MMA(c-1)) ----
        if (c + 1 < NCHUNK) {
            const int k0n = (c + 1) * KC;
            const uint32_t bb = smem_base + BOFF + ((c + 1) & 1) * BBYTES;
            #pragma unroll
            for (int it = 0; it < 4; ++it)
                CP_ASYNC16(bb + (uint32_t)((brb + it * 32) * APAD + c8 * 8) * 2,
                           g_Wpack + (size_t)(brb + it * 32) * DDIM + k0n + c8 * 8);
            CP_COMMIT();
        }

        // ---- compute: 4 k-tiles of 16, per-warp staggered start ----
        #pragma unroll
        for (int j = 0; j < 4; ++j) {
            const int kt = (j + wstag) & 3;
            const uint32_t kOff = (uint32_t)(32 * kt);   // 16 bf16 = 32 bytes

            uint32_t afrag[2][4];
            #pragma unroll
            for (int mt = 0; mt < 2; ++mt)
                LDSM_X4(afrag[mt][0], afrag[mt][1], afrag[mt][2], afrag[mt][3],
                        aStage + aLdsmBase + (uint32_t)(mt * 16 * APAD * 2) + kOff);

            #pragma unroll
            for (int pr = 0; pr < 2; ++pr) {             // two n-group pairs
                uint32_t b0a, b1a, b0b, b1b;
                LDSM_X4(b0a, b1a, b0b, b1b,
                        bStage + bLdsmBase + (uint32_t)(pr * 16 * APAD * 2) + kOff);
                #pragma unroll
                for (int mt = 0; mt < 2; ++mt) {
                    asm volatile(
                        "mma.sync.aligned.m16n8k16.row.col.f32.bf16.bf16.f32 "
                        "{%0,%1,%2,%3}, {%4,%5,%6,%7}, {%8,%9}, {%0,%1,%2,%3};"
                        : "+f"(acc[mt][2 * pr][0]), "+f"(acc[mt][2 * pr][1]),
                          "+f"(acc[mt][2 * pr][2]), "+f"(acc[mt][2 * pr][3])
                        : "r"(afrag[mt][0]), "r"(afrag[mt][1]),
                          "r"(afrag[mt][2]), "r"(afrag[mt][3]),
                          "r"(b0a), "r"(b1a));
                    asm volatile(
                        "mma.sync.aligned.m16n8k16.row.col.f32.bf16.bf16.f32 "
                        "{%0,%1,%2,%3}, {%4,%5,%6,%7}, {%8,%9}, {%0,%1,%2,%3};"
                        : "+f"(acc[mt][2 * pr + 1][0]), "+f"(acc[mt][2 * pr + 1][1]),
                          "+f"(acc[mt][2 * pr + 1][2]), "+f"(acc[mt][2 * pr + 1][3])
                        : "r"(afrag[mt][0]), "r"(afrag[mt][1]),
                          "r"(afrag[mt][2]), "r"(afrag[mt][3]),
                          "r"(b0b), "r"(b1b));
                }
            }
        }
    }
    __syncthreads();   // MMAs done; stage buffers dead -> reuse smem as outS

    // --- scatter accumulators to fp32 out tile ---
    #pragma unroll
    for (int mt = 0; mt < 2; ++mt) {
        #pragma unroll
        for (int nt = 0; nt < 4; ++nt) {
            const int r = warp_m + mt * 16 + gid;
            const int col = warp_n + nt * 8 + tig * 2;
            *reinterpret_cast<float2*>(outS + r * OPAD + col) =
                make_float2(acc[mt][nt][0], acc[mt][nt][1]);
            *reinterpret_cast<float2*>(outS + (r + 8) * OPAD + col) =
                make_float2(acc[mt][nt][2], acc[mt][nt][3]);
        }
    }
    __syncthreads();

    // --- per-row epilogue: softmax gates, expert mix, sigmoid heads ---
    if (tid < TILE_M) {
        const float* rowv = outS + tid * OPAD;

        float g[2][10];
        #pragma unroll
        for (int t = 0; t < 2; ++t) {
            float s = 0.0f;
            #pragma unroll
            for (int e = 0; e < 10; ++e) {
                float l = rowv[100 + t * 10 + e] + gate_b[t * 10 + e];
                float ex = expf(l);
                g[t][e] = ex; s += ex;
            }
            float inv = 1.0f / s;
            #pragma unroll
            for (int e = 0; e < 10; ++e) g[t][e] *= inv;
        }

        float ti0[10], ti1[10];
        #pragma unroll
        for (int u = 0; u < 10; ++u) { ti0[u] = 0.0f; ti1[u] = 0.0f; }
        #pragma unroll
        for (int e = 0; e < 10; ++e) {
            const float g0 = g[0][e], g1 = g[1][e];
            #pragma unroll
            for (int u = 0; u < 10; ++u) {
                const int j = e * 10 + u;
                float v = fmaxf(rowv[j] + expert_b[j], 0.0f);
                ti0[u] += v * g0;
                ti1[u] += v * g1;
            }
        }

        float zc = ctr_b[0], zv = cvr_b[0];
        #pragma unroll
        for (int u = 0; u < 10; ++u) {
            zc += ti0[u] * ctr_w[u];
            zv += ti1[u] * cvr_w[u];
        }
        const int gr = row0 + tid;
        out[gr]         = 1.0f / (1.0f + expf(-zc));
        out[BROWS + gr] = 1.0f / (1.0f + expf(-zv));
    }
}

// ---------------- launch ----------------
extern "C" void kernel_launch(void* const* d_in, const int* in_sizes, int n_in,
                              void* d_out, int out_size) {
    const float* x        = (const float*)d_in[0];
    const float* expert_w = (const float*)d_in[3];
    const float* expert_b = (const float*)d_in[4];
    const float* gate_w   = (const float*)d_in[5];
    const float* gate_b   = (const float*)d_in[6];
    const float* ctr_w    = (const float*)d_in[7];
    const float* ctr_b    = (const float*)d_in[8];
    const float* cvr_w    = (const float*)d_in[9];
    const float* cvr_b    = (const float*)d_in[10];
    float* out = (float*)d_out;

    cudaFuncSetAttribute(mmoe_main_kernel,
                         cudaFuncAttributeMaxDynamicSharedMemorySize, SMEM_BYTES);

    pack_weights_kernel<<<dim3(NCOLS, 8), 128>>>(expert_w, gate_w);
    mmoe_main_kernel<<<BROWS / TILE_M, 256, SMEM_BYTES>>>(
        x, expert_b, gate_b, ctr_w, ctr_b, cvr_w, cvr_b, out);
}

// round 9
// speedup vs baseline: 1.2257x; 1.0283x over previous
#include <cuda_runtime.h>
#include <cuda_bf16.h>
#include <cstdint>

// ---------------- problem constants ----------------
#define BROWS   65536
#define DDIM    1024
#define NCOLS   128      // 120 real columns padded to 128
#define KC      64       // K elems staged per chunk
#define NCHUNK  (DDIM / KC)   // 16
#define TILE_M  128
#define APAD    72       // smem row pitch (bf16): 144B rows -> conflict-free LDSM
#define OPAD    130      // out-tile row pitch (floats)

#define ABYTES  (TILE_M * APAD * 2)     // 18432 per A buffer
#define BOFF    (2 * ABYTES)            // 36864
#define BBYTES  (NCOLS * APAD * 2)      // 18432 per B buffer
#define SMEM_BYTES (BOFF + 2 * BBYTES)  // 73728 (>= out tile 128*130*4=66560)

// packed weights: [NCOLS][DDIM] K-major bf16 (256 KB static device array — no alloc)
__device__ __align__(16) __nv_bfloat16 g_Wpack[NCOLS * DDIM];

__device__ __forceinline__ uint32_t smem_u32(const void* p) {
    uint32_t a;
    asm("{ .reg .u64 t; cvta.to.shared.u64 t, %1; cvt.u32.u64 %0, t; }" : "=r"(a) : "l"(p));
    return a;
}
#define CP_ASYNC16(dst_u32, src_ptr) \
    asm volatile("cp.async.cg.shared.global [%0], [%1], 16;" :: "r"(dst_u32), "l"(src_ptr) : "memory")
#define CP_COMMIT() asm volatile("cp.async.commit_group;" ::: "memory")
#define CP_WAIT0()  asm volatile("cp.async.wait_group 0;" ::: "memory")
#define LDSM_X4(r0, r1, r2, r3, addr) \
    asm volatile("ldmatrix.sync.aligned.m8n8.x4.shared.b16 {%0,%1,%2,%3}, [%4];" \
                 : "=r"(r0), "=r"(r1), "=r"(r2), "=r"(r3) : "r"(addr))

// ---------------- weight pack kernel (grid 128 x 8, 128 thr) ----------------
__global__ void pack_weights_kernel(const float* __restrict__ expert_w,
                                    const float* __restrict__ gate_w) {
    const int j = blockIdx.x;                          // 0..127 (output col)
    const int d = blockIdx.y * 128 + threadIdx.x;      // 0..1023
    float v = 0.0f;
    if (j < 100) {
        int e = j / 10, u = j % 10;
        v = expert_w[((size_t)e * DDIM + d) * 10 + u];
    } else if (j < 120) {
        int idx = j - 100;
        int t = idx / 10, e = idx % 10;
        v = gate_w[((size_t)t * DDIM + d) * 10 + e];
    }
    g_Wpack[(size_t)j * DDIM + d] = __float2bfloat16(v);
}

// ---------------- fused MMoE main kernel (128x128 tile, 2 CTAs/SM) ----------------
extern "C" __global__ void __launch_bounds__(256, 2)
mmoe_main_kernel(const float* __restrict__ x,
                 const float* __restrict__ expert_b,   // [10,10]
                 const float* __restrict__ gate_b,     // [2,10]
                 const float* __restrict__ ctr_w,      // [10]
                 const float* __restrict__ ctr_b,      // [1]
                 const float* __restrict__ cvr_w,      // [10]
                 const float* __restrict__ cvr_b,      // [1]
                 float* __restrict__ out) {            // [2*B] = [ctr | cvr]
    extern __shared__ char smem[];
    const uint32_t smem_base = smem_u32(smem);
    float* outS = reinterpret_cast<float*>(smem);

    const int tid  = threadIdx.x;
    const int wid  = tid >> 5;
    const int lane = tid & 31;
    const int gid  = lane >> 2;   // 0..7
    const int tig  = lane & 3;    // 0..3
    const int warp_m = (wid & 3) * 32;    // 4 warps along M (128 rows)
    const int warp_n = (wid >> 2) * 64;   // 2 warps along N (128 cols)
    const int row0 = blockIdx.x * TILE_M;
    const int wstag = wid & 3;            // per-warp kt phase stagger

    // ldmatrix per-lane base byte offsets (within a stage buffer)
    const uint32_t aLdsmBase =
        (uint32_t)(warp_m + ((lane >> 3) & 1) * 8 + (lane & 7)) * (APAD * 2)
        + ((lane >> 4) & 1) * 16;
    const uint32_t bLdsmBase =
        (uint32_t)(warp_n + ((lane >> 4) & 1) * 8 + (lane & 7)) * (APAD * 2)
        + ((lane >> 3) & 1) * 16;

    // load-mapping ids
    const int rbase = tid >> 4;          // A: 0..15, rows rbase + it*16 (it<8)
    const int c4    = tid & 15;          // col float4
    const int brb   = tid >> 3;          // B: 0..31, rows brb + it*32 (it<4)
    const int c8    = tid & 7;           // col uint4

    float acc[2][8][4];
    #pragma unroll
    for (int mt = 0; mt < 2; ++mt)
        #pragma unroll
        for (int nt = 0; nt < 8; ++nt)
            #pragma unroll
            for (int i = 0; i < 4; ++i) acc[mt][nt][i] = 0.0f;

    // ---- prologue: prefetch chunk 0 ----
    float4 av[8];
    #pragma unroll
    for (int it = 0; it < 8; ++it)
        av[it] = *reinterpret_cast<const float4*>(
            x + (size_t)(row0 + rbase + it * 16) * DDIM + c4 * 4);
    {
        const uint32_t bb = smem_base + BOFF;         // bbuf[0]
        #pragma unroll
        for (int it = 0; it < 4; ++it)
            CP_ASYNC16(bb + (uint32_t)((brb + it * 32) * APAD + c8 * 8) * 2,
                       g_Wpack + (size_t)(brb + it * 32) * DDIM + c8 * 8);
        CP_COMMIT();
    }

    for (int c = 0; c < NCHUNK; ++c) {
        __nv_bfloat16* Ab = reinterpret_cast<__nv_bfloat16*>(smem + (c & 1) * ABYTES);
        const uint32_t aStage = smem_base + (c & 1) * ABYTES;
        const uint32_t bStage = smem_base + BOFF + (c & 1) * BBYTES;

        // ---- STS: convert prefetched A regs -> abuf[c&1] ----
        #pragma unroll
        for (int it = 0; it < 8; ++it) {
            __nv_bfloat162 lo = __floats2bfloat162_rn(av[it].x, av[it].y);
            __nv_bfloat162 hi = __floats2bfloat162_rn(av[it].z, av[it].w);
            uint2 pk;
            pk.x = *reinterpret_cast<uint32_t*>(&lo);
            pk.y = *reinterpret_cast<uint32_t*>(&hi);
            *reinterpret_cast<uint2*>(Ab + (rbase + it * 16) * APAD + c4 * 4) = pk;
        }

        // ---- prefetch A chunk c+1 into regs ----
        if (c + 1 < NCHUNK) {
            const int k0n = (c + 1) * KC;
            #pragma unroll
            for (int it = 0; it < 8; ++it)
                av[it] = *reinterpret_cast<const float4*>(
                    x + (size_t)(row0 + rbase + it * 16) * DDIM + k0n + c4 * 4);
        }

        CP_WAIT0();          // B(c) landed (overlapped MMA(c-1))
        __syncthreads();     // A(c)/B(c) staged; prev MMAs retired

        // ---- issue B chunk c+1 (buffer free: all warps past MMA(c-1)) ----
        if (c + 1 < NCHUNK) {
            const int k0n = (c + 1) * KC;
            const uint32_t bb = smem_base + BOFF + ((c + 1) & 1) * BBYTES;
            #pragma unroll
            for (int it = 0; it < 4; ++it)
                CP_ASYNC16(bb + (uint32_t)((brb + it * 32) * APAD + c8 * 8) * 2,
                           g_Wpack + (size_t)(brb + it * 32) * DDIM + k0n + c8 * 8);
            CP_COMMIT();
        }

        // ---- compute: 4 k-tiles of 16, per-warp staggered start ----
        #pragma unroll
        for (int j = 0; j < 4; ++j) {
            const int kt = (j + wstag) & 3;
            const uint32_t kOff = (uint32_t)(32 * kt);   // 16 bf16 = 32 bytes

            uint32_t afrag[2][4];
            #pragma unroll
            for (int mt = 0; mt < 2; ++mt)
                LDSM_X4(afrag[mt][0], afrag[mt][1], afrag[mt][2], afrag[mt][3],
                        aStage + aLdsmBase + (uint32_t)(mt * 16 * APAD * 2) + kOff);

            #pragma unroll
            for (int pr = 0; pr < 4; ++pr) {             // four n-group pairs (64 cols)
                uint32_t b0a, b1a, b0b, b1b;
                LDSM_X4(b0a, b1a, b0b, b1b,
                        bStage + bLdsmBase + (uint32_t)(pr * 16 * APAD * 2) + kOff);
                #pragma unroll
                for (int mt = 0; mt < 2; ++mt) {
                    asm volatile(
                        "mma.sync.aligned.m16n8k16.row.col.f32.bf16.bf16.f32 "
                        "{%0,%1,%2,%3}, {%4,%5,%6,%7}, {%8,%9}, {%0,%1,%2,%3};"
                        : "+f"(acc[mt][2 * pr][0]), "+f"(acc[mt][2 * pr][1]),
                          "+f"(acc[mt][2 * pr][2]), "+f"(acc[mt][2 * pr][3])
                        : "r"(afrag[mt][0]), "r"(afrag[mt][1]),
                          "r"(afrag[mt][2]), "r"(afrag[mt][3]),
                          "r"(b0a), "r"(b1a));
                    asm volatile(
                        "mma.sync.aligned.m16n8k16.row.col.f32.bf16.bf16.f32 "
                        "{%0,%1,%2,%3}, {%4,%5,%6,%7}, {%8,%9}, {%0,%1,%2,%3};"
                        : "+f"(acc[mt][2 * pr + 1][0]), "+f"(acc[mt][2 * pr + 1][1]),
                          "+f"(acc[mt][2 * pr + 1][2]), "+f"(acc[mt][2 * pr + 1][3])
                        : "r"(afrag[mt][0]), "r"(afrag[mt][1]),
                          "r"(afrag[mt][2]), "r"(afrag[mt][3]),
                          "r"(b0b), "r"(b1b));
                }
            }
        }
    }
    __syncthreads();   // MMAs done; stage buffers dead -> reuse smem as outS

    // --- scatter accumulators to fp32 out tile ---
    #pragma unroll
    for (int mt = 0; mt < 2; ++mt) {
        #pragma unroll
        for (int nt = 0; nt < 8; ++nt) {
            const int r = warp_m + mt * 16 + gid;
            const int col = warp_n + nt * 8 + tig * 2;
            *reinterpret_cast<float2*>(outS + r * OPAD + col) =
                make_float2(acc[mt][nt][0], acc[mt][nt][1]);
            *reinterpret_cast<float2*>(outS + (r + 8) * OPAD + col) =
                make_float2(acc[mt][nt][2], acc[mt][nt][3]);
        }
    }
    __syncthreads();

    // --- per-row epilogue: softmax gates, expert mix, sigmoid heads ---
    if (tid < TILE_M) {
        const float* rowv = outS + tid * OPAD;

        float g[2][10];
        #pragma unroll
        for (int t = 0; t < 2; ++t) {
            float s = 0.0f;
            #pragma unroll
            for (int e = 0; e < 10; ++e) {
                float l = rowv[100 + t * 10 + e] + gate_b[t * 10 + e];
                float ex = expf(l);
                g[t][e] = ex; s += ex;
            }
            float inv = 1.0f / s;
            #pragma unroll
            for (int e = 0; e < 10; ++e) g[t][e] *= inv;
        }

        float ti0[10], ti1[10];
        #pragma unroll
        for (int u = 0; u < 10; ++u) { ti0[u] = 0.0f; ti1[u] = 0.0f; }
        #pragma unroll
        for (int e = 0; e < 10; ++e) {
            const float g0 = g[0][e], g1 = g[1][e];
            #pragma unroll
            for (int u = 0; u < 10; ++u) {
                const int j = e * 10 + u;
                float v = fmaxf(rowv[j] + expert_b[j], 0.0f);
                ti0[u] += v * g0;
                ti1[u] += v * g1;
            }
        }

        float zc = ctr_b[0], zv = cvr_b[0];
        #pragma unroll
        for (int u = 0; u < 10; ++u) {
            zc += ti0[u] * ctr_w[u];
            zv += ti1[u] * cvr_w[u];
        }
        const int gr = row0 + tid;
        out[gr]         = 1.0f / (1.0f + expf(-zc));
        out[BROWS + gr] = 1.0f / (1.0f + expf(-zv));
    }
}

// ---------------- launch ----------------
extern "C" void kernel_launch(void* const* d_in, const int* in_sizes, int n_in,
                              void* d_out, int out_size) {
    const float* x        = (const float*)d_in[0];
    const float* expert_w = (const float*)d_in[3];
    const float* expert_b = (const float*)d_in[4];
    const float* gate_w   = (const float*)d_in[5];
    const float* gate_b   = (const float*)d_in[6];
    const float* ctr_w    = (const float*)d_in[7];
    const float* ctr_b    = (const float*)d_in[8];
    const float* cvr_w    = (const float*)d_in[9];
    const float* cvr_b    = (const float*)d_in[10];
    float* out = (float*)d_out;

    cudaFuncSetAttribute(mmoe_main_kernel,
                         cudaFuncAttributeMaxDynamicSharedMemorySize, SMEM_BYTES);

    pack_weights_kernel<<<dim3(NCOLS, 8), 128>>>(expert_w, gate_w);
    mmoe_main_kernel<<<BROWS / TILE_M, 256, SMEM_BYTES>>>(
        x, expert_b, gate_b, ctr_w, ctr_b, cvr_w, cvr_b, out);
}